// round 1
// baseline (speedup 1.0000x reference)
#include <cuda_runtime.h>
#include <cuda_bf16.h>

#define NN 16
#define DIM 64

// One warp per batch element. Lane l owns output dims {2l, 2l+1} as float2.
__global__ void __launch_bounds__(128, 8) klgcn_kernel(
    const int* __restrict__ u,
    const int* __restrict__ v,
    const int* __restrict__ user_neighbor,
    const int* __restrict__ item_neighbor,
    const int* __restrict__ adj_ent,
    const int* __restrict__ adj_rel,
    const float* __restrict__ usr_emb,
    const float* __restrict__ ent_emb,
    const float* __restrict__ rel_emb,
    const float* __restrict__ agg_W,
    const float* __restrict__ agg_b,
    float* __restrict__ out,
    int batch)
{
    const int warp = (blockIdx.x * blockDim.x + threadIdx.x) >> 5;
    const int lane = threadIdx.x & 31;
    if (warp >= batch) return;
    const int b = warp;
    const unsigned FULL = 0xffffffffu;

    const float2* __restrict__ usr2 = (const float2*)usr_emb;
    const float2* __restrict__ ent2 = (const float2*)ent_emb;
    const float2* __restrict__ rel2 = (const float2*)rel_emb;
    const float2* __restrict__ W2   = (const float2*)agg_W;
    const float2* __restrict__ b2   = (const float2*)agg_b;

    const int uu = u[b];
    const int vv = v[b];

    // lanes 0..15 own one neighbor slot each (lanes 16..31 duplicate -> broadcast, free)
    const int nsl = lane & 15;
    const int in_idx = item_neighbor[b * NN + nsl];   // -> usr_emb gather
    const int un_idx = user_neighbor[b * NN + nsl];   // -> ent_emb gather
    const int ae_idx = adj_ent[vv * NN + nsl];        // neighbor entities of v
    const int ar_idx = adj_rel[vv * NN + nsl];        // neighbor relations of v

    const float2 user_e = usr2[uu * 32 + lane];
    const float2 item_o = ent2[vv * 32 + lane];

    // ---- lite_user / lite_item: mean of 16 gathered rows each ----
    float2 lite_u = make_float2(0.f, 0.f);
    float2 lite_i = make_float2(0.f, 0.f);
    #pragma unroll
    for (int n = 0; n < NN; n++) {
        const int i1 = __shfl_sync(FULL, in_idx, n);
        const int i2 = __shfl_sync(FULL, un_idx, n);
        const float2 a = usr2[i1 * 32 + lane];
        const float2 c = ent2[i2 * 32 + lane];
        lite_u.x += a.x; lite_u.y += a.y;
        lite_i.x += c.x; lite_i.y += c.y;
    }

    // ---- ur_scores[n] = <user_e, rel_emb[nbr_rel[n]]>, butterfly-reduced ----
    float sc[NN];
    #pragma unroll
    for (int n = 0; n < NN; n++) {
        const int r = __shfl_sync(FULL, ar_idx, n);
        const float2 re = rel2[r * 32 + lane];
        float p = user_e.x * re.x + user_e.y * re.y;
        p += __shfl_xor_sync(FULL, p, 16);
        p += __shfl_xor_sync(FULL, p, 8);
        p += __shfl_xor_sync(FULL, p, 4);
        p += __shfl_xor_sync(FULL, p, 2);
        p += __shfl_xor_sync(FULL, p, 1);
        sc[n] = p;   // every lane holds all 16 scores
    }

    // ---- softmax over the 16 scores (redundant per lane, no sync needed) ----
    float m = sc[0];
    #pragma unroll
    for (int n = 1; n < NN; n++) m = fmaxf(m, sc[n]);
    float ssum = 0.f;
    #pragma unroll
    for (int n = 0; n < NN; n++) { sc[n] = __expf(sc[n] - m); ssum += sc[n]; }
    const float inv = 1.0f / ssum;

    // ---- attention-weighted neighbor aggregation ----
    float2 agg = make_float2(0.f, 0.f);
    #pragma unroll
    for (int n = 0; n < NN; n++) {
        const int e = __shfl_sync(FULL, ae_idx, n);
        const float2 ev = ent2[e * 32 + lane];
        const float w = sc[n] * inv;
        agg.x += w * ev.x;
        agg.y += w * ev.y;
    }
    const float2 comb = make_float2(item_o.x + agg.x, item_o.y + agg.y);

    // ---- item_emb = tanh(combined @ W + bias) : distributed matvec ----
    float2 acc = b2[lane];
    #pragma unroll
    for (int j = 0; j < 32; j++) {
        const float cx = __shfl_sync(FULL, comb.x, j);   // combined[2j]
        const float cy = __shfl_sync(FULL, comb.y, j);   // combined[2j+1]
        const float2 w0 = W2[(2 * j)     * 32 + lane];   // W[2j  ][2l..2l+1]
        const float2 w1 = W2[(2 * j + 1) * 32 + lane];   // W[2j+1][2l..2l+1]
        acc.x += cx * w0.x + cy * w1.x;
        acc.y += cx * w0.y + cy * w1.y;
    }
    const float2 item_e = make_float2(tanhf(acc.x), tanhf(acc.y));

    // ---- final blend + dot + sigmoid ----
    const float inv_n = 1.0f / (float)NN;
    const float ufx = 0.5f * (lite_u.x * inv_n) + 0.5f * user_e.x;
    const float ufy = 0.5f * (lite_u.y * inv_n) + 0.5f * user_e.y;
    const float ifx = 0.5f * (lite_i.x * inv_n) + 0.5f * item_e.x;
    const float ify = 0.5f * (lite_i.y * inv_n) + 0.5f * item_e.y;

    float p = ufx * ifx + ufy * ify;
    p += __shfl_xor_sync(FULL, p, 16);
    p += __shfl_xor_sync(FULL, p, 8);
    p += __shfl_xor_sync(FULL, p, 4);
    p += __shfl_xor_sync(FULL, p, 2);
    p += __shfl_xor_sync(FULL, p, 1);

    if (lane == 0) {
        out[b] = 1.0f / (1.0f + __expf(-p));
    }
}

extern "C" void kernel_launch(void* const* d_in, const int* in_sizes, int n_in,
                              void* d_out, int out_size) {
    const int*   u             = (const int*)d_in[0];
    const int*   v             = (const int*)d_in[1];
    const int*   user_neighbor = (const int*)d_in[2];
    const int*   item_neighbor = (const int*)d_in[3];
    const int*   adj_ent       = (const int*)d_in[4];
    const int*   adj_rel       = (const int*)d_in[5];
    const float* usr_emb       = (const float*)d_in[6];
    const float* ent_emb       = (const float*)d_in[7];
    const float* rel_emb       = (const float*)d_in[8];
    const float* agg_W         = (const float*)d_in[9];
    const float* agg_b         = (const float*)d_in[10];
    float*       out           = (float*)d_out;

    const int batch = in_sizes[0];
    // one warp per element, 4 warps per block
    const int threads = 128;
    const int blocks = (batch * 32 + threads - 1) / threads;
    klgcn_kernel<<<blocks, threads>>>(u, v, user_neighbor, item_neighbor,
                                      adj_ent, adj_rel, usr_emb, ent_emb,
                                      rel_emb, agg_W, agg_b, out, batch);
}